// round 2
// baseline (speedup 1.0000x reference)
#include <cuda_runtime.h>

// Problem constants
#define MA      100001      // N_ATOMS + 1
#define MB      200001      // N_BONDS + 1
#define N_AT    100000
#define NMOL    2048
#define HID     300
#define AFD     133
#define BFD     147
#define MAXNB   6

// Scratch (static device globals; allocated at module load, not in kernel_launch)
__device__ float g_binput[(size_t)MB * HID];   // 240 MB
__device__ float g_bmsgA [(size_t)MB * HID];   // 240 MB
__device__ float g_bmsgB [(size_t)MB * HID];   // 240 MB
__device__ float g_amsg  [(size_t)MA * HID];   // 120 MB
__device__ float g_counts[NMOL];

// ---------------------------------------------------------------------------
// Tiled SGEMM, 128x128 block tile, 8x8 microtile, 256 threads.
// MODE 0: b_input = f_bonds @ W_i ; b_msgA = relu(b_input)
// MODE 1: bmsg_wr = relu(b_input + (amsg[b2a[m]] - bmsg_rd[b2revb[m]]) @ W_h)
//         (gather fused into the A-tile loader; ping-pong via pp flag)
// MODE 2: atom_hiddens = relu(concat(f_atoms, amsg) @ W_o + b_o), fused
//         atomicAdd segment-sum into molsum for rows >= 1.
// ---------------------------------------------------------------------------
#define BM 128
#define BN 128
#define BK 8
#define TM 8
#define TN 8

template <int MODE>
__global__ __launch_bounds__(256, 2)
void gemm_kernel(int M, int K,
                 const float* __restrict__ A,        // MODE0: f_bonds, MODE2: f_atoms
                 const int*   __restrict__ idxA,     // MODE1: b2a
                 const int*   __restrict__ idxB,     // MODE1: b2revb
                 const float* __restrict__ W,
                 const float* __restrict__ bias,     // MODE2: b_o
                 const int*   __restrict__ mol_ids,  // MODE2
                 float*       __restrict__ molsum,   // MODE2: d_out
                 int pp)                             // MODE1 ping-pong: 0 read A write B, 1 read B write A
{
    __shared__ float As[BK][BM];
    __shared__ float Bs[BK][BN];
    __shared__ int   sIA[BM];
    __shared__ int   sIB[BM];

    const int tid = threadIdx.x;
    const int m0  = blockIdx.y * BM;
    const int n0  = blockIdx.x * BN;

    const float* bmsg_rd = (pp == 0) ? g_bmsgA : g_bmsgB;
    float*       bmsg_wr = (pp == 0) ? g_bmsgB : g_bmsgA;

    if (MODE == 1) {
        for (int i = tid; i < BM; i += 256) {
            int gm = m0 + i;
            sIA[i] = (gm < M) ? idxA[gm] : 0;
            sIB[i] = (gm < M) ? idxB[gm] : 0;
        }
        __syncthreads();
    }

    const int tx = tid & 15;
    const int ty = tid >> 4;

    float acc[TM][TN];
#pragma unroll
    for (int i = 0; i < TM; i++)
#pragma unroll
        for (int j = 0; j < TN; j++) acc[i][j] = 0.f;

    const int bk_row = tid >> 5;        // 0..7
    const int bk_col = (tid & 31) * 4;  // 0..124

    for (int k0 = 0; k0 < K; k0 += BK) {
        // --- A tile: 128x8, 4 scalar elements per thread ---
#pragma unroll
        for (int i = 0; i < 4; i++) {
            int lin = tid * 4 + i;
            int m = lin >> 3;
            int k = lin & 7;
            int gm = m0 + m;
            int gk = k0 + k;
            float v = 0.f;
            if (gm < M && gk < K) {
                if (MODE == 0) {
                    v = A[(long)gm * BFD + gk];
                } else if (MODE == 1) {
                    v = g_amsg[(long)sIA[m] * HID + gk]
                      - bmsg_rd[(long)sIB[m] * HID + gk];
                } else {
                    v = (gk < AFD) ? A[(long)gm * AFD + gk]
                                   : g_amsg[(long)gm * HID + (gk - AFD)];
                }
            }
            As[k][m] = v;
        }
        // --- B tile: 8x128, float4 per thread (N=300 is 16B aligned) ---
        {
            int gk = k0 + bk_row;
            int gn = n0 + bk_col;
            float4 v = make_float4(0.f, 0.f, 0.f, 0.f);
            if (gk < K && gn < HID) v = *(const float4*)&W[(long)gk * HID + gn];
            *(float4*)&Bs[bk_row][bk_col] = v;
        }
        __syncthreads();

#pragma unroll
        for (int kk = 0; kk < BK; kk++) {
            float a[TM], b[TN];
#pragma unroll
            for (int i = 0; i < TM; i++) a[i] = As[kk][ty * TM + i];
#pragma unroll
            for (int j = 0; j < TN; j++) b[j] = Bs[kk][tx * TN + j];
#pragma unroll
            for (int i = 0; i < TM; i++)
#pragma unroll
                for (int j = 0; j < TN; j++)
                    acc[i][j] += a[i] * b[j];
        }
        __syncthreads();
    }

    // --- epilogue ---
#pragma unroll
    for (int i = 0; i < TM; i++) {
        int gm = m0 + ty * TM + i;
        if (gm >= M) continue;
        int molrow = -1;
        if (MODE == 2 && gm >= 1) molrow = mol_ids[gm - 1];
#pragma unroll
        for (int j = 0; j < TN; j++) {
            int gn = n0 + tx * TN + j;
            if (gn >= HID) continue;
            float v = acc[i][j];
            long o = (long)gm * HID + gn;
            if (MODE == 0) {
                g_binput[o] = v;
                g_bmsgA[o]  = fmaxf(v, 0.f);
            } else if (MODE == 1) {
                bmsg_wr[o] = fmaxf(g_binput[o] + v, 0.f);
            } else {
                float r = fmaxf(v + bias[gn], 0.f);
                if (molrow >= 0)
                    atomicAdd(&molsum[(long)molrow * HID + gn], r);
            }
        }
    }
}

// ---------------------------------------------------------------------------
// a_message[a] = sum_{j<6} bmsg[a2b[a][j]]   (float4 vectorized, 75x4 block)
// src: 0 -> g_bmsgA, 1 -> g_bmsgB
// ---------------------------------------------------------------------------
__global__ void gather_sum_kernel(const int* __restrict__ a2b, int src)
{
    const float* bmsg = (src == 0) ? g_bmsgA : g_bmsgB;
    int atom = blockIdx.x * 4 + threadIdx.y;
    if (atom >= MA) return;
    int c = threadIdx.x * 4;            // 0..296
    const int* row = a2b + (long)atom * MAXNB;
    float4 s = make_float4(0.f, 0.f, 0.f, 0.f);
#pragma unroll
    for (int j = 0; j < MAXNB; j++) {
        float4 v = *(const float4*)&bmsg[(long)row[j] * HID + c];
        s.x += v.x; s.y += v.y; s.z += v.z; s.w += v.w;
    }
    *(float4*)&g_amsg[(long)atom * HID + c] = s;
}

__global__ void zero_kernel(float* __restrict__ out)
{
    int i = blockIdx.x * 256 + threadIdx.x;
    if (i < NMOL * HID) out[i] = 0.f;
    if (i < NMOL) g_counts[i] = 0.f;
}

__global__ void count_kernel(const int* __restrict__ mol_ids)
{
    int i = blockIdx.x * 256 + threadIdx.x;
    if (i < N_AT) atomicAdd(&g_counts[mol_ids[i]], 1.f);
}

__global__ void divide_kernel(float* __restrict__ out)
{
    int i = blockIdx.x * 256 + threadIdx.x;
    if (i < NMOL * HID) out[i] = out[i] / fmaxf(g_counts[i / HID], 1.f);
}

// ---------------------------------------------------------------------------
extern "C" void kernel_launch(void* const* d_in, const int* in_sizes, int n_in,
                              void* d_out, int out_size)
{
    const float* f_atoms = (const float*)d_in[0];
    const float* f_bonds = (const float*)d_in[1];
    const float* W_i     = (const float*)d_in[2];
    const float* W_h     = (const float*)d_in[3];
    const float* W_o     = (const float*)d_in[4];
    const float* b_o     = (const float*)d_in[5];
    const int*   a2b     = (const int*)d_in[6];
    const int*   b2a     = (const int*)d_in[7];
    const int*   b2revb  = (const int*)d_in[8];
    const int*   mol_ids = (const int*)d_in[9];
    float* out = (float*)d_out;

    // init output + counts
    zero_kernel<<<(NMOL * HID + 255) / 256, 256>>>(out);
    count_kernel<<<(N_AT + 255) / 256, 256>>>(mol_ids);

    dim3 blk(256);
    dim3 gridB((HID + BN - 1) / BN, (MB + BM - 1) / BM);   // 3 x 1563
    dim3 gridA((HID + BN - 1) / BN, (MA + BM - 1) / BM);   // 3 x 782
    dim3 gblk(75, 4);
    int  ggrid = (MA + 3) / 4;

    // b_input = f_bonds @ W_i ; bmsgA = relu(b_input)
    gemm_kernel<0><<<gridB, blk>>>(MB, BFD, f_bonds, nullptr, nullptr,
                                   W_i, nullptr, nullptr, nullptr, 0);

    // 2 message-passing iterations (ping-pong A <-> B)
    // it 0: gather from A, gemm reads A writes B
    gather_sum_kernel<<<ggrid, gblk>>>(a2b, 0);
    gemm_kernel<1><<<gridB, blk>>>(MB, HID, nullptr, b2a, b2revb,
                                   W_h, nullptr, nullptr, nullptr, 0);
    // it 1: gather from B, gemm reads B writes A
    gather_sum_kernel<<<ggrid, gblk>>>(a2b, 1);
    gemm_kernel<1><<<gridB, blk>>>(MB, HID, nullptr, b2a, b2revb,
                                   W_h, nullptr, nullptr, nullptr, 1);

    // final gather from A
    gather_sum_kernel<<<ggrid, gblk>>>(a2b, 0);

    // atom_hiddens = relu([f_atoms, amsg] @ W_o + b_o), fused segment-sum
    gemm_kernel<2><<<gridA, blk>>>(MA, AFD + HID, f_atoms, nullptr, nullptr,
                                   W_o, b_o, mol_ids, out, 0);

    // mean
    divide_kernel<<<(NMOL * HID + 255) / 256, 256>>>(out);
}

// round 3
// speedup vs baseline: 2.0069x; 2.0069x over previous
#include <cuda_runtime.h>
#include <cstdint>

// Problem constants
#define MA      100001      // N_ATOMS + 1
#define MB      200001      // N_BONDS + 1
#define N_AT    100000
#define NMOL    2048
#define HID     300
#define AFD     133
#define BFD     147
#define MAXNB   6

// Scratch (static device globals)
__device__ float g_binput[(size_t)MB * HID];   // 240 MB
__device__ float g_bmsgA [(size_t)MB * HID];   // 240 MB
__device__ float g_bmsgB [(size_t)MB * HID];   // 240 MB
__device__ float g_amsg  [(size_t)MA * HID];   // 120 MB
__device__ float g_counts[NMOL];

// ---------------------------------------------------------------------------
// TF32 tensor-core GEMM. Block tile 64 x 320 (full HID width in one pass),
// BK=16, 256 threads = 8 warps as 2(m) x 4(n); warp tile 32 x 80
// = 2 m-frags x 10 n-frags of m16n8k8.
// MODE 0: b_input = f_bonds @ W_i ; bmsgA = relu(b_input)
// MODE 1: bmsg_wr = relu(b_input + (amsg[b2a[m]] - bmsg_rd[b2revb[m]]) @ W_h)
// MODE 2: relu(concat(f_atoms, amsg) @ W_o + b_o) -> atomic segment sum
// ---------------------------------------------------------------------------
#define BM 64
#define BN 320
#define BK 16
#define AS_STRIDE 72    // 72 % 32 == 8 -> conflict-free frag reads
#define BS_STRIDE 328   // 328 % 32 == 8 -> conflict-free frag reads

__device__ __forceinline__ uint32_t f2tf(float f) {
    uint32_t u;
    asm("cvt.rna.tf32.f32 %0, %1;" : "=r"(u) : "f"(f));
    return u;
}

__device__ __forceinline__ void mma_tf32(float d[4], const uint32_t a[4],
                                         const uint32_t b[2]) {
    asm volatile(
        "mma.sync.aligned.m16n8k8.row.col.f32.tf32.tf32.f32 "
        "{%0,%1,%2,%3}, {%4,%5,%6,%7}, {%8,%9}, {%0,%1,%2,%3};\n"
        : "+f"(d[0]), "+f"(d[1]), "+f"(d[2]), "+f"(d[3])
        : "r"(a[0]), "r"(a[1]), "r"(a[2]), "r"(a[3]), "r"(b[0]), "r"(b[1]));
}

template <int MODE>
__global__ __launch_bounds__(256)
void mma_gemm(int M, int K,
              const float* __restrict__ A,        // MODE0: f_bonds, MODE2: f_atoms
              const int*   __restrict__ idxA,     // MODE1: b2a
              const int*   __restrict__ idxB,     // MODE1: b2revb
              const float* __restrict__ W,
              const float* __restrict__ bias,     // MODE2
              const int*   __restrict__ mol_ids,  // MODE2
              float*       __restrict__ molsum,   // MODE2
              int pp)
{
    __shared__ uint32_t As[BK * AS_STRIDE];
    __shared__ uint32_t Bs[BK * BS_STRIDE];

    const int tid = threadIdx.x;
    const int m0  = blockIdx.x * BM;

    const float* bmsg_rd = (pp == 0) ? g_bmsgA : g_bmsgB;
    float*       bmsg_wr = (pp == 0) ? g_bmsgB : g_bmsgA;

    // ---- loader thread mapping: A: thread -> (row lm, 4 consecutive k) ----
    const int lm = tid >> 2;          // 0..63
    const int kq = (tid & 3) * 4;     // 0,4,8,12
    const int gm_l = m0 + lm;
    const bool valid_m = gm_l < M;
    int ia = 0, ib = 0;
    if (MODE == 1) {
        int g = valid_m ? gm_l : 0;
        ia = idxA[g];
        ib = idxB[g];
    }

    // ---- warp / fragment mapping ----
    const int lane = tid & 31, wid = tid >> 5;
    const int warp_m = wid & 1;       // 0..1
    const int warp_n = wid >> 1;      // 0..3
    const int r = lane >> 2;          // groupID
    const int c = lane & 3;           // tid-in-group

    float acc[2][10][4];
#pragma unroll
    for (int f = 0; f < 2; f++)
#pragma unroll
        for (int j = 0; j < 10; j++)
#pragma unroll
            for (int q = 0; q < 4; q++) acc[f][j][q] = 0.f;

    float  av[4];
    float4 bv[5];

    const int KITER = (K + BK - 1) / BK;

    // ---------------- prefetch k0 = 0 ----------------
    {
        const int k0 = 0;
        if (MODE == 1) {
            int gk0 = k0 + kq;
            float4 va = *(const float4*)&g_amsg[(size_t)ia * HID + gk0];
            float4 vb = *(const float4*)&bmsg_rd[(size_t)ib * HID + gk0];
            av[0] = va.x - vb.x; av[1] = va.y - vb.y;
            av[2] = va.z - vb.z; av[3] = va.w - vb.w;
        } else {
#pragma unroll
            for (int i = 0; i < 4; i++) {
                int gk = k0 + kq + i;
                float v = 0.f;
                if (valid_m && gk < K) {
                    if (MODE == 0) v = A[(size_t)gm_l * BFD + gk];
                    else v = (gk < AFD) ? A[(size_t)gm_l * AFD + gk]
                                        : g_amsg[(size_t)gm_l * HID + (gk - AFD)];
                }
                av[i] = v;
            }
        }
#pragma unroll
        for (int it = 0; it < 5; it++) {
            int l = tid + 256 * it;
            int k = l / 80, c4 = (l % 80) * 4;
            int gk = k0 + k;
            float4 v = make_float4(0.f, 0.f, 0.f, 0.f);
            if (gk < K && c4 < HID) v = *(const float4*)&W[(size_t)gk * HID + c4];
            bv[it] = v;
        }
    }

    for (int kt = 0; kt < KITER; kt++) {
        // ---- stage regs -> SMEM (tf32 convert) ----
#pragma unroll
        for (int i = 0; i < 4; i++)
            As[(kq + i) * AS_STRIDE + lm] = f2tf(av[i]);
#pragma unroll
        for (int it = 0; it < 5; it++) {
            int l = tid + 256 * it;
            int k = l / 80, c4 = (l % 80) * 4;
            uint32_t* p = &Bs[k * BS_STRIDE + c4];
            p[0] = f2tf(bv[it].x); p[1] = f2tf(bv[it].y);
            p[2] = f2tf(bv[it].z); p[3] = f2tf(bv[it].w);
        }
        __syncthreads();

        // ---- prefetch next tile (overlaps with MMA below) ----
        if (kt + 1 < KITER) {
            const int k0 = (kt + 1) * BK;
            if (MODE == 1) {
                int gk0 = k0 + kq;
                if (gk0 < HID) {
                    float4 va = *(const float4*)&g_amsg[(size_t)ia * HID + gk0];
                    float4 vb = *(const float4*)&bmsg_rd[(size_t)ib * HID + gk0];
                    av[0] = va.x - vb.x; av[1] = va.y - vb.y;
                    av[2] = va.z - vb.z; av[3] = va.w - vb.w;
                } else {
                    av[0] = av[1] = av[2] = av[3] = 0.f;
                }
            } else {
#pragma unroll
                for (int i = 0; i < 4; i++) {
                    int gk = k0 + kq + i;
                    float v = 0.f;
                    if (valid_m && gk < K) {
                        if (MODE == 0) v = A[(size_t)gm_l * BFD + gk];
                        else v = (gk < AFD) ? A[(size_t)gm_l * AFD + gk]
                                            : g_amsg[(size_t)gm_l * HID + (gk - AFD)];
                    }
                    av[i] = v;
                }
            }
#pragma unroll
            for (int it = 0; it < 5; it++) {
                int l = tid + 256 * it;
                int k = l / 80, c4 = (l % 80) * 4;
                int gk = k0 + k;
                float4 v = make_float4(0.f, 0.f, 0.f, 0.f);
                if (gk < K && c4 < HID) v = *(const float4*)&W[(size_t)gk * HID + c4];
                bv[it] = v;
            }
        }

        // ---- MMA over staged tile ----
#pragma unroll
        for (int ks = 0; ks < 2; ks++) {
            uint32_t a[2][4];
#pragma unroll
            for (int f = 0; f < 2; f++) {
                int mb = warp_m * 32 + f * 16;
                a[f][0] = As[(ks * 8 + c) * AS_STRIDE + mb + r];
                a[f][1] = As[(ks * 8 + c) * AS_STRIDE + mb + r + 8];
                a[f][2] = As[(ks * 8 + c + 4) * AS_STRIDE + mb + r];
                a[f][3] = As[(ks * 8 + c + 4) * AS_STRIDE + mb + r + 8];
            }
#pragma unroll
            for (int j = 0; j < 10; j++) {
                int nb = warp_n * 80 + j * 8;
                uint32_t b[2];
                b[0] = Bs[(ks * 8 + c) * BS_STRIDE + nb + r];
                b[1] = Bs[(ks * 8 + c + 4) * BS_STRIDE + nb + r];
                mma_tf32(acc[0][j], a[0], b);
                mma_tf32(acc[1][j], a[1], b);
            }
        }
        __syncthreads();
    }

    // ---------------- epilogue ----------------
#pragma unroll
    for (int f = 0; f < 2; f++) {
        int row0 = m0 + warp_m * 32 + f * 16 + r;
        int mol0 = -1, mol1 = -1;
        if (MODE == 2) {
            if (row0 >= 1 && row0 < M) mol0 = mol_ids[row0 - 1];
            if (row0 + 8 >= 1 && row0 + 8 < M) mol1 = mol_ids[row0 + 7];
        }
#pragma unroll
        for (int j = 0; j < 10; j++) {
            int col0 = warp_n * 80 + j * 8 + 2 * c;
            if (col0 >= HID) continue;
#pragma unroll
            for (int h = 0; h < 2; h++) {
                int gm = row0 + h * 8;
                if (gm >= M) continue;
                float2 v2 = make_float2(acc[f][j][h * 2], acc[f][j][h * 2 + 1]);
                size_t o = (size_t)gm * HID + col0;
                if (MODE == 0) {
                    *(float2*)&g_binput[o] = v2;
                    *(float2*)&g_bmsgA[o] =
                        make_float2(fmaxf(v2.x, 0.f), fmaxf(v2.y, 0.f));
                } else if (MODE == 1) {
                    float2 bi = *(const float2*)&g_binput[o];
                    *(float2*)&bmsg_wr[o] =
                        make_float2(fmaxf(bi.x + v2.x, 0.f), fmaxf(bi.y + v2.y, 0.f));
                } else {
                    int mo = h ? mol1 : mol0;
                    if (mo >= 0) {
                        float r0 = fmaxf(v2.x + bias[col0], 0.f);
                        float r1 = fmaxf(v2.y + bias[col0 + 1], 0.f);
                        atomicAdd(&molsum[(size_t)mo * HID + col0], r0);
                        atomicAdd(&molsum[(size_t)mo * HID + col0 + 1], r1);
                    }
                }
            }
        }
    }
}

// ---------------------------------------------------------------------------
// a_message[a] = sum_{j<6} bmsg[a2b[a][j]]   (float4, 75x4 block)
// ---------------------------------------------------------------------------
__global__ void gather_sum_kernel(const int* __restrict__ a2b, int src)
{
    const float* bmsg = (src == 0) ? g_bmsgA : g_bmsgB;
    int atom = blockIdx.x * 4 + threadIdx.y;
    if (atom >= MA) return;
    int c = threadIdx.x * 4;
    const int* row = a2b + (size_t)atom * MAXNB;
    float4 s = make_float4(0.f, 0.f, 0.f, 0.f);
#pragma unroll
    for (int j = 0; j < MAXNB; j++) {
        float4 v = *(const float4*)&bmsg[(size_t)row[j] * HID + c];
        s.x += v.x; s.y += v.y; s.z += v.z; s.w += v.w;
    }
    *(float4*)&g_amsg[(size_t)atom * HID + c] = s;
}

__global__ void zero_kernel(float* __restrict__ out)
{
    int i = blockIdx.x * 256 + threadIdx.x;
    if (i < NMOL * HID) out[i] = 0.f;
    if (i < NMOL) g_counts[i] = 0.f;
}

__global__ void count_kernel(const int* __restrict__ mol_ids)
{
    int i = blockIdx.x * 256 + threadIdx.x;
    if (i < N_AT) atomicAdd(&g_counts[mol_ids[i]], 1.f);
}

__global__ void divide_kernel(float* __restrict__ out)
{
    int i = blockIdx.x * 256 + threadIdx.x;
    if (i < NMOL * HID) out[i] = out[i] / fmaxf(g_counts[i / HID], 1.f);
}

// ---------------------------------------------------------------------------
extern "C" void kernel_launch(void* const* d_in, const int* in_sizes, int n_in,
                              void* d_out, int out_size)
{
    const float* f_atoms = (const float*)d_in[0];
    const float* f_bonds = (const float*)d_in[1];
    const float* W_i     = (const float*)d_in[2];
    const float* W_h     = (const float*)d_in[3];
    const float* W_o     = (const float*)d_in[4];
    const float* b_o     = (const float*)d_in[5];
    const int*   a2b     = (const int*)d_in[6];
    const int*   b2a     = (const int*)d_in[7];
    const int*   b2revb  = (const int*)d_in[8];
    const int*   mol_ids = (const int*)d_in[9];
    float* out = (float*)d_out;

    zero_kernel<<<(NMOL * HID + 255) / 256, 256>>>(out);
    count_kernel<<<(N_AT + 255) / 256, 256>>>(mol_ids);

    dim3 blk(256);
    int gridB = (MB + BM - 1) / BM;   // 3126
    int gridA = (MA + BM - 1) / BM;   // 1563
    dim3 gblk(75, 4);
    int  ggrid = (MA + 3) / 4;

    // b_input = f_bonds @ W_i ; bmsgA = relu(b_input)
    mma_gemm<0><<<gridB, blk>>>(MB, BFD, f_bonds, nullptr, nullptr,
                                W_i, nullptr, nullptr, nullptr, 0);

    // message passing iteration 0: gather from A, gemm reads A writes B
    gather_sum_kernel<<<ggrid, gblk>>>(a2b, 0);
    mma_gemm<1><<<gridB, blk>>>(MB, HID, nullptr, b2a, b2revb,
                                W_h, nullptr, nullptr, nullptr, 0);
    // iteration 1: gather from B, gemm reads B writes A
    gather_sum_kernel<<<ggrid, gblk>>>(a2b, 1);
    mma_gemm<1><<<gridB, blk>>>(MB, HID, nullptr, b2a, b2revb,
                                W_h, nullptr, nullptr, nullptr, 1);

    // final gather from A
    gather_sum_kernel<<<ggrid, gblk>>>(a2b, 0);

    // relu(concat(f_atoms, amsg) @ W_o + b_o) + fused segment sum
    mma_gemm<2><<<gridA, blk>>>(MA, AFD + HID, f_atoms, nullptr, nullptr,
                                W_o, b_o, mol_ids, out, 0);

    divide_kernel<<<(NMOL * HID + 255) / 256, 256>>>(out);
}

// round 6
// speedup vs baseline: 5.4288x; 2.7050x over previous
#include <cuda_runtime.h>
#include <cuda_fp16.h>
#include <cstdint>

// ---------------------------------------------------------------------------
// Problem constants
// ---------------------------------------------------------------------------
#define MA      100001      // N_ATOMS + 1
#define MB      200001      // N_BONDS + 1
#define N_AT    100000
#define NMOL    2048
#define HID     300
#define AFD     133
#define BFD     147
#define MAXNB   6

#define NPAD    320
#define MBP     200064      // MB padded to 64
#define MAP     100096      // MA padded to 64
#define KCH0    10          // GEMM0: K=147 -> 160
#define KCH1    20          // GEMM1: K=300 -> 320
#define KCH2    29          // GEMM2: 9 planes f_atoms (144) + 20 planes amsg (320)

// ---------------------------------------------------------------------------
// Device buffers (static globals; no allocation anywhere)
// ---------------------------------------------------------------------------
__device__ __align__(16) __half g_fb16[(size_t)MBP * 160];    //  64 MB fp16 f_bonds
__device__ __align__(16) __half g_fa16[(size_t)MAP * 144];    //  29 MB fp16 f_atoms
__device__ __align__(16) __half g_pre [(size_t)MBP * NPAD];   // 128 MB
__device__ __align__(16) __half g_bmsg[(size_t)MB  * NPAD];   // 128 MB
__device__ __align__(16) __half g_amsg[(size_t)MAP * NPAD];   //  64 MB
__device__ __align__(16) float  g_binput[(size_t)MB * NPAD];  // 256 MB
__device__ __align__(16) __half g_wt0[KCH0 * NPAD * 16];
__device__ __align__(16) __half g_wt1[KCH1 * NPAD * 16];
__device__ __align__(16) __half g_wt2[KCH2 * NPAD * 16];
__device__ float g_counts[NMOL];

// ---------------------------------------------------------------------------
// Helpers
// ---------------------------------------------------------------------------
__device__ __forceinline__ uint32_t smem_u32(const void* p) {
    uint32_t a;
    asm("{ .reg .u64 t; cvta.to.shared.u64 t, %1; cvt.u32.u64 %0, t; }"
        : "=r"(a) : "l"(p));
    return a;
}

#define CP_ASYNC16(dst, src) \
    asm volatile("cp.async.cg.shared.global [%0], [%1], 16;" :: "r"(dst), "l"(src) : "memory")
#define CP_COMMIT()  asm volatile("cp.async.commit_group;" ::: "memory")
#define CP_WAIT2()   asm volatile("cp.async.wait_group 2;" ::: "memory")

#define LDSM_X4(r0, r1, r2, r3, addr) \
    asm volatile("ldmatrix.sync.aligned.m8n8.x4.shared.b16 {%0,%1,%2,%3}, [%4];" \
                 : "=r"(r0), "=r"(r1), "=r"(r2), "=r"(r3) : "r"(addr))

__device__ __forceinline__ void mma16816(float d[4], const uint32_t a[4],
                                         const uint32_t b[2]) {
    asm volatile(
        "mma.sync.aligned.m16n8k16.row.col.f32.f16.f16.f32 "
        "{%0,%1,%2,%3},{%4,%5,%6,%7},{%8,%9},{%0,%1,%2,%3};"
        : "+f"(d[0]), "+f"(d[1]), "+f"(d[2]), "+f"(d[3])
        : "r"(a[0]), "r"(a[1]), "r"(a[2]), "r"(a[3]), "r"(b[0]), "r"(b[1]));
}

// 16B-chunk XOR swizzle: within a row, chunk slot = row*2 + (sel ^ ((row>>2)&1)).
// Makes every 8-lane ldmatrix phase hit 32 distinct banks.
__device__ __forceinline__ int SWZ(int r) { return (r >> 2) & 1; }

// ---------------------------------------------------------------------------
// GEMM: block = 64 rows x 320 cols, 256 threads = 8 warps (2m x 4n),
// warp tile 32m x 80n. 4-stage cp.async pipeline, k-chunk = 16.
// Stage layout: A 64 rows x 32B at +0 (2048B), B 320 rows x 32B at +2048.
// MODE 0: A=g_fb16[.][160]           -> binput=D (f32), bmsg=relu(D)
// MODE 1: A=g_pre[.][320]            -> bmsg=relu(binput+D)
// MODE 2: A=g_fa16|g_amsg (split K)  -> atomicAdd(out[mol], relu(D+bias))
// ---------------------------------------------------------------------------
#define STAGE_B 12288

template <int MODE>
__device__ __forceinline__ void issue_stage(uint32_t sb, int kc, int m0, int tid)
{
    uint32_t base = sb + (uint32_t)(kc & 3) * STAGE_B;
    const __half* wt = (MODE == 0) ? g_wt0 : (MODE == 1) ? g_wt1 : g_wt2;
#pragma unroll
    for (int it = 0; it < 3; it++) {
        int u = tid + it * 256;
        uint32_t dst;
        const __half* src;
        if (u < 128) {
            int r = u >> 1, sel = u & 1;
            int grow = m0 + r;
            if (MODE == 0)
                src = g_fb16 + (size_t)grow * 160 + kc * 16 + sel * 8;
            else if (MODE == 1)
                src = g_pre + (size_t)grow * NPAD + kc * 16 + sel * 8;
            else
                src = (kc < 9)
                    ? g_fa16 + (size_t)grow * 144 + kc * 16 + sel * 8
                    : g_amsg + (size_t)grow * NPAD + (kc - 9) * 16 + sel * 8;
            dst = base + (uint32_t)((r * 2 + (sel ^ SWZ(r))) * 16);
        } else {
            int v = u - 128;                         // 0..639
            src = wt + (size_t)kc * (NPAD * 16) + v * 8;
            dst = base + 2048 + (uint32_t)(v * 16);
        }
        CP_ASYNC16(dst, src);
    }
    CP_COMMIT();
}

template <int MODE, int KCH>
__global__ __launch_bounds__(256)
void tc_gemm(int M, const float* __restrict__ bias,
             const int* __restrict__ mol_ids, float* __restrict__ out)
{
    __shared__ __align__(16) char smem[4 * STAGE_B];
    const uint32_t sb = smem_u32(smem);
    const int tid  = threadIdx.x;
    const int lane = tid & 31;
    const int wid  = tid >> 5;
    const int wm   = wid & 1;
    const int wn   = wid >> 1;
    const int m0   = blockIdx.x * 64;

    // fragment ldmatrix offsets (bytes within a stage)
    uint32_t Aoff[2], Boff[5];
    {
        int sel = lane >> 4;
#pragma unroll
        for (int mf = 0; mf < 2; mf++) {
            int r = wm * 32 + mf * 16 + (lane & 15);
            Aoff[mf] = (uint32_t)((r * 2 + (sel ^ SWZ(r))) * 16);
        }
    }
    {
        int sel = (lane >> 3) & 1;
        int nb  = (lane & 7) + ((lane >> 4) & 1) * 8;
#pragma unroll
        for (int jp = 0; jp < 5; jp++) {
            int n = wn * 80 + jp * 16 + nb;
            Boff[jp] = (uint32_t)(2048 + (n * 2 + (sel ^ SWZ(n))) * 16);
        }
    }

    float acc[2][10][4];
#pragma unroll
    for (int mf = 0; mf < 2; mf++)
#pragma unroll
        for (int j = 0; j < 10; j++)
#pragma unroll
            for (int q = 0; q < 4; q++) acc[mf][j][q] = 0.f;

    issue_stage<MODE>(sb, 0, m0, tid);
    issue_stage<MODE>(sb, 1, m0, tid);
    issue_stage<MODE>(sb, 2, m0, tid);

    for (int kc = 0; kc < KCH; kc++) {
        CP_WAIT2();
        __syncthreads();
        const uint32_t stg = sb + (uint32_t)(kc & 3) * STAGE_B;

        uint32_t a[2][4];
#pragma unroll
        for (int mf = 0; mf < 2; mf++)
            LDSM_X4(a[mf][0], a[mf][1], a[mf][2], a[mf][3], stg + Aoff[mf]);
        uint32_t b[10][2];
#pragma unroll
        for (int jp = 0; jp < 5; jp++) {
            uint32_t r0, r1, r2, r3;
            LDSM_X4(r0, r1, r2, r3, stg + Boff[jp]);
            b[2 * jp][0] = r0; b[2 * jp][1] = r1;       // n-group jp*16+0..7
            b[2 * jp + 1][0] = r2; b[2 * jp + 1][1] = r3; // n-group jp*16+8..15
        }

        if (kc + 3 < KCH) issue_stage<MODE>(sb, kc + 3, m0, tid);

#pragma unroll
        for (int mf = 0; mf < 2; mf++)
#pragma unroll
            for (int j = 0; j < 10; j++)
                mma16816(acc[mf][j], a[mf], b[j]);
    }

    // -------- epilogue --------
    const int g   = lane >> 2;
    const int tig = lane & 3;
#pragma unroll
    for (int mf = 0; mf < 2; mf++) {
#pragma unroll
        for (int h = 0; h < 2; h++) {
            int gm = m0 + wm * 32 + mf * 16 + g + h * 8;
            if (gm >= M) continue;
            int mol = -1;
            if (MODE == 2) {
                if (gm >= 1) mol = mol_ids[gm - 1];
                if (mol < 0) continue;
            }
#pragma unroll
            for (int j = 0; j < 10; j++) {
                int col = wn * 80 + j * 8 + tig * 2;
                float vx = acc[mf][j][h * 2];
                float vy = acc[mf][j][h * 2 + 1];
                if (MODE == 0) {
                    size_t o = (size_t)gm * NPAD + col;
                    *(float2*)&g_binput[o] = make_float2(vx, vy);
                    *(__half2*)&g_bmsg[o] =
                        __floats2half2_rn(fmaxf(vx, 0.f), fmaxf(vy, 0.f));
                } else if (MODE == 1) {
                    size_t o = (size_t)gm * NPAD + col;
                    float2 bi = *(const float2*)&g_binput[o];
                    *(__half2*)&g_bmsg[o] =
                        __floats2half2_rn(fmaxf(bi.x + vx, 0.f), fmaxf(bi.y + vy, 0.f));
                } else {
                    if (col < HID) {
                        atomicAdd(&out[(size_t)mol * HID + col],     fmaxf(vx + bias[col], 0.f));
                        atomicAdd(&out[(size_t)mol * HID + col + 1], fmaxf(vy + bias[col + 1], 0.f));
                    }
                }
            }
        }
    }
}

// ---------------------------------------------------------------------------
// gather: amsg[a] = sum_j bmsg[a2b[a][j]]   (fp32 accumulate, fp16 store)
// ---------------------------------------------------------------------------
__global__ void gather_kernel(const int* __restrict__ a2b)
{
    int atom = blockIdx.x * 6 + threadIdx.y;
    if (atom >= MA) return;
    int tx = threadIdx.x;                 // 0..39, 8 halves each
    const int* row = a2b + (size_t)atom * MAXNB;
    float2 acc[4] = {{0,0},{0,0},{0,0},{0,0}};
#pragma unroll
    for (int j = 0; j < MAXNB; j++) {
        uint4 v = *(const uint4*)(g_bmsg + (size_t)row[j] * NPAD + tx * 8);
        const __half2* hp = (const __half2*)&v;
#pragma unroll
        for (int q = 0; q < 4; q++) {
            float2 f = __half22float2(hp[q]);
            acc[q].x += f.x; acc[q].y += f.y;
        }
    }
    uint4 u;
    __half2* up = (__half2*)&u;
#pragma unroll
    for (int q = 0; q < 4; q++) up[q] = __float22half2_rn(acc[q]);
    *(uint4*)(g_amsg + (size_t)atom * NPAD + tx * 8) = u;
}

// pre[m] = amsg[b2a[m]] - bmsg[b2revb[m]]
__global__ void pre_kernel(const int* __restrict__ b2a, const int* __restrict__ b2revb)
{
    int bond = blockIdx.x * 6 + threadIdx.y;
    if (bond >= MB) return;
    int tx = threadIdx.x;
    int ia = b2a[bond], ib = b2revb[bond];
    uint4 va = *(const uint4*)(g_amsg + (size_t)ia * NPAD + tx * 8);
    uint4 vb = *(const uint4*)(g_bmsg + (size_t)ib * NPAD + tx * 8);
    const __half2* ap = (const __half2*)&va;
    const __half2* bp = (const __half2*)&vb;
    uint4 u; __half2* up = (__half2*)&u;
#pragma unroll
    for (int q = 0; q < 4; q++) up[q] = __hsub2(ap[q], bp[q]);
    *(uint4*)(g_pre + (size_t)bond * NPAD + tx * 8) = u;
}

// ---------------------------------------------------------------------------
// prep kernels
// ---------------------------------------------------------------------------
__global__ void prep_fb(const float* __restrict__ f_bonds)
{
    long i = blockIdx.x * 256L + threadIdx.x;
    if (i >= (long)MBP * 20) return;
    long m = i / 20; int t = (int)(i % 20);
    int k0 = t * 8;
    __half h[8];
#pragma unroll
    for (int q = 0; q < 8; q++) {
        int k = k0 + q;
        h[q] = (m < MB && k < BFD) ? __float2half_rn(f_bonds[m * BFD + k]) : __half(0.f);
    }
    *(uint4*)(g_fb16 + (size_t)m * 160 + k0) = *(uint4*)h;
}

__global__ void prep_fa(const float* __restrict__ f_atoms)
{
    long i = blockIdx.x * 256L + threadIdx.x;
    if (i >= (long)MAP * 18) return;
    long m = i / 18; int t = (int)(i % 18);
    int k0 = t * 8;
    __half h[8];
#pragma unroll
    for (int q = 0; q < 8; q++) {
        int k = k0 + q;
        h[q] = (m < MA && k < AFD) ? __float2half_rn(f_atoms[m * AFD + k]) : __half(0.f);
    }
    *(uint4*)(g_fa16 + (size_t)m * 144 + k0) = *(uint4*)h;
}

// weights: fp16, k-planar [plane][320][16], swizzle baked per n-row
__global__ void prep_w(const float* __restrict__ Wi, const float* __restrict__ Wh,
                       const float* __restrict__ Wo)
{
    int i = blockIdx.x * 256 + threadIdx.x;
    const int I0 = 320 * 2 * KCH0, I1 = 320 * 2 * KCH1, I2 = 320 * 2 * KCH2;
    if (i >= I0 + I1 + I2) return;
    const float* W; __half* dst; int n, t, which;
    if (i < I0)            { W = Wi; dst = g_wt0; n = i / (2*KCH0); t = i % (2*KCH0); which = 0; }
    else if (i < I0 + I1)  { int j = i - I0; W = Wh; dst = g_wt1; n = j / (2*KCH1); t = j % (2*KCH1); which = 1; }
    else                   { int j = i - I0 - I1; W = Wo; dst = g_wt2; n = j / (2*KCH2); t = j % (2*KCH2); which = 2; }
    int plane = t >> 1, sel = t & 1;
    __half h[8];
#pragma unroll
    for (int q = 0; q < 8; q++) {
        int kk = plane * 16 + sel * 8 + q;
        float v = 0.f;
        if (n < HID) {
            if (which == 0)      { if (kk < BFD) v = W[(size_t)kk * HID + n]; }
            else if (which == 1) { if (kk < HID) v = W[(size_t)kk * HID + n]; }
            else {
                if (plane < 9) { if (kk < AFD) v = W[(size_t)kk * HID + n]; }
                else {
                    int k2 = (plane - 9) * 16 + sel * 8 + q;
                    if (k2 < HID) v = W[(size_t)(AFD + k2) * HID + n];
                }
            }
        }
        h[q] = __float2half_rn(v);
    }
    *(uint4*)(dst + ((size_t)plane * NPAD + n) * 16 + (sel ^ SWZ(n)) * 8) = *(uint4*)h;
}

// ---------------------------------------------------------------------------
__global__ void zero_kernel(float* __restrict__ out)
{
    int i = blockIdx.x * 256 + threadIdx.x;
    if (i < NMOL * HID) out[i] = 0.f;
    if (i < NMOL) g_counts[i] = 0.f;
}
__global__ void count_kernel(const int* __restrict__ mol_ids)
{
    int i = blockIdx.x * 256 + threadIdx.x;
    if (i < N_AT) atomicAdd(&g_counts[mol_ids[i]], 1.f);
}
__global__ void divide_kernel(float* __restrict__ out)
{
    int i = blockIdx.x * 256 + threadIdx.x;
    if (i < NMOL * HID) out[i] = out[i] / fmaxf(g_counts[i / HID], 1.f);
}

// ---------------------------------------------------------------------------
extern "C" void kernel_launch(void* const* d_in, const int* in_sizes, int n_in,
                              void* d_out, int out_size)
{
    const float* f_atoms = (const float*)d_in[0];
    const float* f_bonds = (const float*)d_in[1];
    const float* W_i     = (const float*)d_in[2];
    const float* W_h     = (const float*)d_in[3];
    const float* W_o     = (const float*)d_in[4];
    const float* b_o     = (const float*)d_in[5];
    const int*   a2b     = (const int*)d_in[6];
    const int*   b2a     = (const int*)d_in[7];
    const int*   b2revb  = (const int*)d_in[8];
    const int*   mol_ids = (const int*)d_in[9];
    float* out = (float*)d_out;

    const int gridB = MBP / 64;       // 3126
    const int gridA = MAP / 64;       // 1564
    dim3 gblk(40, 6);
    const int ggA = (MA + 5) / 6;
    const int ggB = (MB + 5) / 6;
    const int wItems = 320 * 2 * (KCH0 + KCH1 + KCH2);

    zero_kernel<<<(NMOL * HID + 255) / 256, 256>>>(out);                   // 0
    count_kernel<<<(N_AT + 255) / 256, 256>>>(mol_ids);                    // 1
    prep_fb<<<(int)(((long)MBP * 20 + 255) / 256), 256>>>(f_bonds);        // 2
    prep_fa<<<(int)(((long)MAP * 18 + 255) / 256), 256>>>(f_atoms);        // 3
    prep_w<<<(wItems + 255) / 256, 256>>>(W_i, W_h, W_o);                  // 4

    tc_gemm<0, KCH0><<<gridB, 256>>>(MB, nullptr, nullptr, nullptr);       // 5 <- profiled
    gather_kernel<<<ggA, gblk>>>(a2b);                                     // 6
    pre_kernel<<<ggB, gblk>>>(b2a, b2revb);                                // 7
    tc_gemm<1, KCH1><<<gridB, 256>>>(MB, nullptr, nullptr, nullptr);       // 8
    gather_kernel<<<ggA, gblk>>>(a2b);                                     // 9
    pre_kernel<<<ggB, gblk>>>(b2a, b2revb);                                // 10
    tc_gemm<1, KCH1><<<gridB, 256>>>(MB, nullptr, nullptr, nullptr);       // 11
    gather_kernel<<<ggA, gblk>>>(a2b);                                     // 12
    tc_gemm<2, KCH2><<<gridA, 256>>>(MA, b_o, mol_ids, out);               // 13
    divide_kernel<<<(NMOL * HID + 255) / 256, 256>>>(out);                 // 14
}